// round 5
// baseline (speedup 1.0000x reference)
#include <cuda_runtime.h>
#include <cstdint>

// ---------------------------------------------------------------------------
// TernaryLinear, legacy-IMMA path (harness targets plain sm_100: no tcgen05).
//   K1: per-row absmax int8 quant of x (single-pass, register-cached row)
//   K2: f32 {-1,0,1} -> int8 weights
//   K3: int8 GEMM mma.sync.m16n8k32, 4 warps @ 64x64, BK=128 (32 iters),
//       3-stage cp.async, 2-stage ldmatrix fragment pipeline, 2 CTA/SM.
// ---------------------------------------------------------------------------

#define T_TOKENS 8192
#define KDIM     4096
#define ODIM     4096

#define BM 128
#define BN 128
#define BK 128             // int8 elems per k-tile (4 mma k-steps)
#define NSTAGE 3
#define KT (KDIM / BK)     // 32
#define A_BYTES (BM * BK)  // 16 KB
#define B_BYTES (BN * BK)  // 16 KB
#define STAGE_BYTES (A_BYTES + B_BYTES)    // 32 KB
#define DYN_SMEM (NSTAGE * STAGE_BYTES + 128)

__device__ __align__(128) int8_t g_xq[(size_t)T_TOKENS * KDIM];
__device__ __align__(128) int8_t g_wq[(size_t)ODIM * KDIM];
__device__ float g_ascale[T_TOKENS];

// --------------------------- helpers ---------------------------------------
__device__ __forceinline__ uint32_t cvta_s(const void* p) {
    return (uint32_t)__cvta_generic_to_shared(p);
}
__device__ __forceinline__ void cp_async16(uint32_t d, const void* s) {
    asm volatile("cp.async.cg.shared.global [%0], [%1], 16;\n" :: "r"(d), "l"(s));
}
__device__ __forceinline__ void cp_commit() {
    asm volatile("cp.async.commit_group;\n" ::: "memory");
}
template <int N> __device__ __forceinline__ void cp_wait() {
    asm volatile("cp.async.wait_group %0;\n" :: "n"(N) : "memory");
}
__device__ __forceinline__ void ldsm_x4(uint32_t* r, uint32_t addr) {
    asm volatile("ldmatrix.sync.aligned.m8n8.x4.shared.b16 {%0,%1,%2,%3}, [%4];"
                 : "=r"(r[0]), "=r"(r[1]), "=r"(r[2]), "=r"(r[3]) : "r"(addr));
}
__device__ __forceinline__ void mma16832(int* d, const uint32_t* a,
                                         uint32_t b0, uint32_t b1) {
    asm volatile(
        "mma.sync.aligned.m16n8k32.row.col.s32.s8.s8.s32 "
        "{%0,%1,%2,%3}, {%4,%5,%6,%7}, {%8,%9}, {%0,%1,%2,%3};\n"
        : "+r"(d[0]), "+r"(d[1]), "+r"(d[2]), "+r"(d[3])
        : "r"(a[0]), "r"(a[1]), "r"(a[2]), "r"(a[3]), "r"(b0), "r"(b1));
}

// ---------------------------------------------------------------------------
// K1: quantize activations (single global read, row in registers)
// ---------------------------------------------------------------------------
__global__ __launch_bounds__(256) void quant_x_kernel(const float* __restrict__ x) {
    const int row = blockIdx.x;
    const float4* xr = reinterpret_cast<const float4*>(x + (size_t)row * KDIM);

    float4 v[4];
    float m = 0.0f;
    #pragma unroll
    for (int i = 0; i < 4; i++) {
        v[i] = xr[threadIdx.x + (i << 8)];
        m = fmaxf(m, fmaxf(fmaxf(fabsf(v[i].x), fabsf(v[i].y)),
                           fmaxf(fabsf(v[i].z), fabsf(v[i].w))));
    }
    #pragma unroll
    for (int o = 16; o; o >>= 1) m = fmaxf(m, __shfl_xor_sync(0xffffffffu, m, o));

    __shared__ float warpmax[8];
    __shared__ float s_inv;
    const int wid = threadIdx.x >> 5, lane = threadIdx.x & 31;
    if (lane == 0) warpmax[wid] = m;
    __syncthreads();
    if (threadIdx.x == 0) {
        float mm = warpmax[0];
        #pragma unroll
        for (int i = 1; i < 8; i++) mm = fmaxf(mm, warpmax[i]);
        float sc = fmaxf(mm, 1e-10f) / 127.0f;
        g_ascale[row] = sc;
        s_inv = 1.0f / sc;
    }
    __syncthreads();
    const float inv = s_inv;

    char4* outq = reinterpret_cast<char4*>(g_xq + (size_t)row * KDIM);
    #pragma unroll
    for (int i = 0; i < 4; i++) {
        char4 c;
        c.x = (signed char)(int)fminf(fmaxf(rintf(v[i].x * inv), -127.0f), 127.0f);
        c.y = (signed char)(int)fminf(fmaxf(rintf(v[i].y * inv), -127.0f), 127.0f);
        c.z = (signed char)(int)fminf(fmaxf(rintf(v[i].z * inv), -127.0f), 127.0f);
        c.w = (signed char)(int)fminf(fmaxf(rintf(v[i].w * inv), -127.0f), 127.0f);
        outq[threadIdx.x + (i << 8)] = c;
    }
}

// ---------------------------------------------------------------------------
// K2: ternary weights f32 -> int8
// ---------------------------------------------------------------------------
__global__ __launch_bounds__(256) void quant_w_kernel(const float* __restrict__ w) {
    const size_t i = (size_t)blockIdx.x * 256 + threadIdx.x;
    const float4 v = reinterpret_cast<const float4*>(w)[i];
    char4 c;
    c.x = (signed char)(int)v.x;
    c.y = (signed char)(int)v.y;
    c.z = (signed char)(int)v.z;
    c.w = (signed char)(int)v.w;
    reinterpret_cast<char4*>(g_wq)[i] = c;
}

// ---------------------------------------------------------------------------
// K3: int8 GEMM. C[T,O] = xq[T,K] @ wq[O,K]^T
// smem rows are 128B (8 chunks of 16B), SW128 swizzle: chunk' = chunk ^ (row&7)
// ks-step advance within a row is XOR with ks*32 (chunk bits disjoint).
// ---------------------------------------------------------------------------
__global__ __launch_bounds__(128, 2)
void gemm_kernel(const float* __restrict__ wscale_p,
                 const float* __restrict__ bias,
                 float* __restrict__ out) {
    extern __shared__ int8_t smem_raw[];
    const uint32_t smem_u = (cvta_s(smem_raw) + 127u) & ~127u;

    const int tid  = threadIdx.x;
    const int lane = tid & 31;
    const int wid  = tid >> 5;
    const int wm   = wid & 1;        // 2 row-groups of 64
    const int wn   = wid >> 1;       // 2 col-groups of 64
    const int bm   = blockIdx.y;
    const int bn   = blockIdx.x;

    const int8_t* Ag = g_xq + (size_t)bm * BM * KDIM;
    const int8_t* Bg = g_wq + (size_t)bn * BN * KDIM;

    // 2048 chunks/tile (A 1024 + B 1024), 128 threads -> 8+8 chunks each
    auto load_tile = [&](int st, int kt) {
        const uint32_t sb = smem_u + st * STAGE_BYTES;
        const int koff = kt * BK;
        #pragma unroll
        for (int r = 0; r < 8; r++) {
            const int id  = tid + (r << 7);
            const int row = id >> 3;
            const int c   = id & 7;
            const uint32_t phys = (uint32_t)((c ^ (row & 7)) << 4);
            cp_async16(sb + row * BK + phys,
                       Ag + (size_t)row * KDIM + koff + (c << 4));
            cp_async16(sb + A_BYTES + row * BK + phys,
                       Bg + (size_t)row * KDIM + koff + (c << 4));
        }
    };

    // ldmatrix offsets for ks=0; ks advance via ^ (ks<<5)
    uint32_t a_off[4];
    {
        const int m  = lane >> 3;
        const int rr = ((m & 1) << 3) + (lane & 7);
        const int cb = m >> 1;
        #pragma unroll
        for (int mi = 0; mi < 4; mi++) {
            const int row = wm * 64 + mi * 16 + rr;
            a_off[mi] = (uint32_t)(row * BK + ((cb ^ (row & 7)) << 4));
        }
    }
    uint32_t b_off[4];
    {
        const int m  = lane >> 3;
        const int cr = ((m >> 1) << 3) + (lane & 7);
        const int cb = m & 1;
        #pragma unroll
        for (int n2 = 0; n2 < 4; n2++) {
            const int col = wn * 64 + n2 * 16 + cr;
            b_off[n2] = (uint32_t)(A_BYTES + col * BK + ((cb ^ (col & 7)) << 4));
        }
    }

    int acc[4][8][4] = {};

    load_tile(0, 0); cp_commit();
    load_tile(1, 1); cp_commit();

    uint32_t a[2][4][4], b[2][4][4];   // double-buffered fragments

    for (int kt = 0; kt < KT; kt++) {
        cp_wait<1>();
        __syncthreads();

        const int nxt = kt + 2;
        if (nxt < KT) load_tile(nxt % NSTAGE, nxt);
        cp_commit();

        const uint32_t sb = smem_u + (kt % NSTAGE) * STAGE_BYTES;

        // prime fragments for ks=0
        #pragma unroll
        for (int mi = 0; mi < 4; mi++) ldsm_x4(a[0][mi], sb + a_off[mi]);
        #pragma unroll
        for (int n2 = 0; n2 < 4; n2++)  ldsm_x4(b[0][n2], sb + b_off[n2]);

        #pragma unroll
        for (int ks = 0; ks < 4; ks++) {
            const int cur = ks & 1, nxtb = cur ^ 1;
            if (ks < 3) {
                const uint32_t kx = (uint32_t)(ks + 1) << 5;
                #pragma unroll
                for (int mi = 0; mi < 4; mi++) ldsm_x4(a[nxtb][mi], sb + (a_off[mi] ^ kx));
                #pragma unroll
                for (int n2 = 0; n2 < 4; n2++)  ldsm_x4(b[nxtb][n2], sb + (b_off[n2] ^ kx));
            }
            #pragma unroll
            for (int mi = 0; mi < 4; mi++) {
                #pragma unroll
                for (int ni = 0; ni < 8; ni++) {
                    const uint32_t* bb = b[cur][ni >> 1];
                    const int o = (ni & 1) << 1;
                    mma16832(acc[mi][ni], a[cur][mi], bb[o], bb[o + 1]);
                }
            }
        }
    }

    // epilogue
    const float ws = __ldg(wscale_p);
    #pragma unroll
    for (int mi = 0; mi < 4; mi++) {
        const int r0 = bm * BM + wm * 64 + mi * 16 + (lane >> 2);
        const float s0 = g_ascale[r0] * ws;
        const float s1 = g_ascale[r0 + 8] * ws;
        #pragma unroll
        for (int ni = 0; ni < 8; ni++) {
            const int c = bn * BN + wn * 64 + ni * 8 + ((lane & 3) << 1);
            const float b0 = __ldg(bias + c);
            const float b1 = __ldg(bias + c + 1);
            float2 v0 = make_float2((float)acc[mi][ni][0] * s0 + b0,
                                    (float)acc[mi][ni][1] * s0 + b1);
            float2 v1 = make_float2((float)acc[mi][ni][2] * s1 + b0,
                                    (float)acc[mi][ni][3] * s1 + b1);
            *reinterpret_cast<float2*>(out + (size_t)r0 * ODIM + c)       = v0;
            *reinterpret_cast<float2*>(out + (size_t)(r0 + 8) * ODIM + c) = v1;
        }
    }
}

// ---------------------------------------------------------------------------
extern "C" void kernel_launch(void* const* d_in, const int* in_sizes, int n_in,
                              void* d_out, int out_size) {
    const float* x      = (const float*)d_in[0];   // [8192, 4096]
    const float* w_t    = (const float*)d_in[1];   // [4096, 4096]
    const float* wscale = (const float*)d_in[2];   // scalar
    const float* bias   = (const float*)d_in[3];   // [4096]
    float* out          = (float*)d_out;           // [8192, 4096]

    quant_x_kernel<<<T_TOKENS, 256>>>(x);
    quant_w_kernel<<<(int)(((size_t)ODIM * KDIM / 4) / 256), 256>>>(w_t);

    cudaFuncSetAttribute(gemm_kernel, cudaFuncAttributeMaxDynamicSharedMemorySize,
                         DYN_SMEM);
    dim3 grid(ODIM / BN, T_TOKENS / BM);   // (32, 64)
    gemm_kernel<<<grid, 128, DYN_SMEM>>>(wscale, bias, out);
}

// round 6
// speedup vs baseline: 1.1052x; 1.1052x over previous
#include <cuda_runtime.h>
#include <cstdint>

// ---------------------------------------------------------------------------
// TernaryLinear, legacy-IMMA path (harness targets plain sm_100: no tcgen05).
//   K1 (fused): per-row absmax int8 quant of x  AND  f32->int8 weight convert
//   K2: int8 GEMM mma.sync.m16n8k32, 4 warps @ 64x64, BK=64, 4-stage cp.async,
//       2 CTA/SM, ldmatrix issued before next-tile cp.async (latency overlap).
// ---------------------------------------------------------------------------

#define T_TOKENS 8192
#define KDIM     4096
#define ODIM     4096

#define BM 128
#define BN 128
#define BK 64              // int8 elems per k-tile
#define NSTAGE 4
#define KT (KDIM / BK)     // 64
#define A_BYTES (BM * BK)  // 8 KB
#define B_BYTES (BN * BK)  // 8 KB
#define STAGE_BYTES (A_BYTES + B_BYTES)    // 16 KB
#define DYN_SMEM (NSTAGE * STAGE_BYTES + 128)

#define W_BLOCKS ((ODIM * KDIM / 4) / 256)   // 16384 blocks for weight convert

__device__ __align__(128) int8_t g_xq[(size_t)T_TOKENS * KDIM];
__device__ __align__(128) int8_t g_wq[(size_t)ODIM * KDIM];
__device__ float g_ascale[T_TOKENS];

// --------------------------- helpers ---------------------------------------
__device__ __forceinline__ uint32_t cvta_s(const void* p) {
    return (uint32_t)__cvta_generic_to_shared(p);
}
__device__ __forceinline__ void cp_async16(uint32_t d, const void* s) {
    asm volatile("cp.async.cg.shared.global [%0], [%1], 16;\n" :: "r"(d), "l"(s));
}
__device__ __forceinline__ void cp_commit() {
    asm volatile("cp.async.commit_group;\n" ::: "memory");
}
template <int N> __device__ __forceinline__ void cp_wait() {
    asm volatile("cp.async.wait_group %0;\n" :: "n"(N) : "memory");
}
__device__ __forceinline__ void ldsm_x4(uint32_t* r, uint32_t addr) {
    asm volatile("ldmatrix.sync.aligned.m8n8.x4.shared.b16 {%0,%1,%2,%3}, [%4];"
                 : "=r"(r[0]), "=r"(r[1]), "=r"(r[2]), "=r"(r[3]) : "r"(addr));
}
__device__ __forceinline__ void mma16832(int* d, const uint32_t* a,
                                         uint32_t b0, uint32_t b1) {
    asm volatile(
        "mma.sync.aligned.m16n8k32.row.col.s32.s8.s8.s32 "
        "{%0,%1,%2,%3}, {%4,%5,%6,%7}, {%8,%9}, {%0,%1,%2,%3};\n"
        : "+r"(d[0]), "+r"(d[1]), "+r"(d[2]), "+r"(d[3])
        : "r"(a[0]), "r"(a[1]), "r"(a[2]), "r"(a[3]), "r"(b0), "r"(b1));
}
__device__ __forceinline__ signed char q8(float v, float inv) {
    return (signed char)(int)fminf(fmaxf(rintf(v * inv), -127.0f), 127.0f);
}

// ---------------------------------------------------------------------------
// K1 fused: blocks [0, 8192) quantize x rows; blocks [8192, +16384) convert w.
// ---------------------------------------------------------------------------
__global__ __launch_bounds__(256) void quant_fused_kernel(
    const float* __restrict__ x, const float* __restrict__ w) {
    if (blockIdx.x < T_TOKENS) {
        const int row = blockIdx.x;
        const float4* xr = reinterpret_cast<const float4*>(x + (size_t)row * KDIM);
        const int base = threadIdx.x << 2;      // 4 consecutive float4 = 16 floats

        float4 v[4];
        float m = 0.0f;
        #pragma unroll
        for (int j = 0; j < 4; j++) {
            v[j] = xr[base + j];
            m = fmaxf(m, fmaxf(fmaxf(fabsf(v[j].x), fabsf(v[j].y)),
                               fmaxf(fabsf(v[j].z), fabsf(v[j].w))));
        }
        #pragma unroll
        for (int o = 16; o; o >>= 1) m = fmaxf(m, __shfl_xor_sync(0xffffffffu, m, o));

        __shared__ float warpmax[8];
        __shared__ float s_inv;
        const int wid = threadIdx.x >> 5, lane = threadIdx.x & 31;
        if (lane == 0) warpmax[wid] = m;
        __syncthreads();
        if (threadIdx.x == 0) {
            float mm = warpmax[0];
            #pragma unroll
            for (int i = 1; i < 8; i++) mm = fmaxf(mm, warpmax[i]);
            float sc = fmaxf(mm, 1e-10f) / 127.0f;
            g_ascale[row] = sc;
            s_inv = 1.0f / sc;
        }
        __syncthreads();
        const float inv = s_inv;

        uint32_t p[4];
        #pragma unroll
        for (int j = 0; j < 4; j++) {
            char4 c = make_char4(q8(v[j].x, inv), q8(v[j].y, inv),
                                 q8(v[j].z, inv), q8(v[j].w, inv));
            p[j] = *reinterpret_cast<uint32_t*>(&c);
        }
        // one 16B store per thread, coalesced
        reinterpret_cast<uint4*>(g_xq + (size_t)row * KDIM)[threadIdx.x] =
            make_uint4(p[0], p[1], p[2], p[3]);
    } else {
        const size_t i = (size_t)(blockIdx.x - T_TOKENS) * 256 + threadIdx.x;
        const float4 v = reinterpret_cast<const float4*>(w)[i];
        char4 c;
        c.x = (signed char)(int)v.x;
        c.y = (signed char)(int)v.y;
        c.z = (signed char)(int)v.z;
        c.w = (signed char)(int)v.w;
        reinterpret_cast<char4*>(g_wq)[i] = c;
    }
}

// ---------------------------------------------------------------------------
// K2: int8 GEMM. C[T,O] = xq[T,K] @ wq[O,K]^T
// smem rows 64B = 4 chunks of 16B; swizzle: phys_chunk = c ^ ((row>>1)&3)
// ---------------------------------------------------------------------------
__global__ __launch_bounds__(128, 2)
void gemm_kernel(const float* __restrict__ wscale_p,
                 const float* __restrict__ bias,
                 float* __restrict__ out) {
    extern __shared__ int8_t smem_raw[];
    const uint32_t smem_u = (cvta_s(smem_raw) + 127u) & ~127u;

    const int tid  = threadIdx.x;
    const int lane = tid & 31;
    const int wid  = tid >> 5;
    const int wm   = wid & 1;        // 2 row-groups of 64
    const int wn   = wid >> 1;       // 2 col-groups of 64
    const int bm   = blockIdx.y;
    const int bn   = blockIdx.x;

    const int8_t* Ag = g_xq + (size_t)bm * BM * KDIM;
    const int8_t* Bg = g_wq + (size_t)bn * BN * KDIM;

    auto load_tile = [&](int st, int kt) {
        const uint32_t sb = smem_u + st * STAGE_BYTES;
        const int koff = kt * BK;
        #pragma unroll
        for (int r = 0; r < 4; r++) {
            const int id  = tid + (r << 7);
            const int row = id >> 2;
            const int c   = id & 3;
            const uint32_t phys = (uint32_t)((c ^ ((row >> 1) & 3)) << 4);
            cp_async16(sb + row * BK + phys,
                       Ag + (size_t)row * KDIM + koff + (c << 4));
            cp_async16(sb + A_BYTES + row * BK + phys,
                       Bg + (size_t)row * KDIM + koff + (c << 4));
        }
    };

    // ldmatrix offsets (ks=0; ks=1 via ^32)
    uint32_t a_off[4];
    {
        const int m  = lane >> 3;
        const int rr = ((m & 1) << 3) + (lane & 7);
        const int cb = m >> 1;
        #pragma unroll
        for (int mi = 0; mi < 4; mi++) {
            const int row = wm * 64 + mi * 16 + rr;
            a_off[mi] = (uint32_t)(row * BK + ((cb ^ ((row >> 1) & 3)) << 4));
        }
    }
    uint32_t b_off[4];
    {
        const int m  = lane >> 3;
        const int cr = ((m >> 1) << 3) + (lane & 7);
        const int cb = m & 1;
        #pragma unroll
        for (int n2 = 0; n2 < 4; n2++) {
            const int col = wn * 64 + n2 * 16 + cr;
            b_off[n2] = (uint32_t)(A_BYTES + col * BK + ((cb ^ ((col >> 1) & 3)) << 4));
        }
    }

    int acc[4][8][4] = {};

    load_tile(0, 0); cp_commit();
    load_tile(1, 1); cp_commit();
    load_tile(2, 2); cp_commit();

    for (int kt = 0; kt < KT; kt++) {
        cp_wait<2>();
        __syncthreads();

        const uint32_t sb = smem_u + (kt & (NSTAGE - 1)) * STAGE_BYTES;

        // issue ks=0 fragment loads first: LDS latency overlaps cp.async burst
        uint32_t a[4][4], b[4][4];
        #pragma unroll
        for (int mi = 0; mi < 4; mi++) ldsm_x4(a[mi], sb + a_off[mi]);
        #pragma unroll
        for (int n2 = 0; n2 < 4; n2++)  ldsm_x4(b[n2], sb + b_off[n2]);

        const int nxt = kt + 3;
        if (nxt < KT) load_tile(nxt & (NSTAGE - 1), nxt);
        cp_commit();

        #pragma unroll
        for (int mi = 0; mi < 4; mi++) {
            #pragma unroll
            for (int ni = 0; ni < 8; ni++) {
                const uint32_t* bb = b[ni >> 1];
                const int o = (ni & 1) << 1;
                mma16832(acc[mi][ni], a[mi], bb[o], bb[o + 1]);
            }
        }

        // ks = 1
        #pragma unroll
        for (int mi = 0; mi < 4; mi++) ldsm_x4(a[mi], sb + (a_off[mi] ^ 32u));
        #pragma unroll
        for (int n2 = 0; n2 < 4; n2++)  ldsm_x4(b[n2], sb + (b_off[n2] ^ 32u));
        #pragma unroll
        for (int mi = 0; mi < 4; mi++) {
            #pragma unroll
            for (int ni = 0; ni < 8; ni++) {
                const uint32_t* bb = b[ni >> 1];
                const int o = (ni & 1) << 1;
                mma16832(acc[mi][ni], a[mi], bb[o], bb[o + 1]);
            }
        }
    }

    // epilogue: y = acc * act_scale[row] * w_scale + bias[col]
    const float ws = __ldg(wscale_p);
    #pragma unroll
    for (int mi = 0; mi < 4; mi++) {
        const int r0 = bm * BM + wm * 64 + mi * 16 + (lane >> 2);
        const float s0 = g_ascale[r0] * ws;
        const float s1 = g_ascale[r0 + 8] * ws;
        #pragma unroll
        for (int ni = 0; ni < 8; ni++) {
            const int c = bn * BN + wn * 64 + ni * 8 + ((lane & 3) << 1);
            const float b0 = __ldg(bias + c);
            const float b1 = __ldg(bias + c + 1);
            float2 v0 = make_float2((float)acc[mi][ni][0] * s0 + b0,
                                    (float)acc[mi][ni][1] * s0 + b1);
            float2 v1 = make_float2((float)acc[mi][ni][2] * s1 + b0,
                                    (float)acc[mi][ni][3] * s1 + b1);
            *reinterpret_cast<float2*>(out + (size_t)r0 * ODIM + c)       = v0;
            *reinterpret_cast<float2*>(out + (size_t)(r0 + 8) * ODIM + c) = v1;
        }
    }
}

// ---------------------------------------------------------------------------
extern "C" void kernel_launch(void* const* d_in, const int* in_sizes, int n_in,
                              void* d_out, int out_size) {
    const float* x      = (const float*)d_in[0];   // [8192, 4096]
    const float* w_t    = (const float*)d_in[1];   // [4096, 4096]
    const float* wscale = (const float*)d_in[2];   // scalar
    const float* bias   = (const float*)d_in[3];   // [4096]
    float* out          = (float*)d_out;           // [8192, 4096]

    quant_fused_kernel<<<T_TOKENS + W_BLOCKS, 256>>>(x, w_t);

    cudaFuncSetAttribute(gemm_kernel, cudaFuncAttributeMaxDynamicSharedMemorySize,
                         DYN_SMEM);
    dim3 grid(ODIM / BN, T_TOKENS / BM);   // (32, 64)
    gemm_kernel<<<grid, 128, DYN_SMEM>>>(wscale, bias, out);
}